// round 14
// baseline (speedup 1.0000x reference)
#include <cuda_runtime.h>
#include <cuda_fp16.h>
#include <math.h>
#include <stdint.h>

#define SEQ 2048
#define DM  2048
#define NH  16
#define DH  128
#define HALF 64

// ---------------- scratch (device globals; allocation-free) ----------------
__device__ float g_cos[SEQ * HALF];
__device__ float g_sin[SEQ * HALF];
__device__ __half g_xh[SEQ * DM];
__device__ __half g_Wqh[DM * DM];   // row-major [K][N] fp16 (no transpose)
__device__ __half g_Wkh[DM * DM];
__device__ __half g_Wvh[DM * DM];
__device__ __half g_Woh[DM * DM];
__device__ __half g_Qh[SEQ * DM];
__device__ __half g_Kh[SEQ * DM];
__device__ __half g_Vth[DM * SEQ];  // V transposed: [col][seq]

// ---------------- helpers ----------------
__device__ __forceinline__ float ex2f(float x) {
    float y;
    asm("ex2.approx.ftz.f32 %0, %1;" : "=f"(y) : "f"(x));
    return y;
}
__device__ __forceinline__ uint32_t pack2h(__half lo, __half hi) {
    __half2 v; v.x = lo; v.y = hi;
    return *(uint32_t*)&v;
}
__device__ __forceinline__ void mma16816(float c[4], const uint32_t a[4], const uint32_t b[2]) {
    asm volatile(
        "mma.sync.aligned.m16n8k16.row.col.f32.f16.f16.f32 "
        "{%0,%1,%2,%3}, {%4,%5,%6,%7}, {%8,%9}, {%0,%1,%2,%3};"
        : "+f"(c[0]), "+f"(c[1]), "+f"(c[2]), "+f"(c[3])
        : "r"(a[0]), "r"(a[1]), "r"(a[2]), "r"(a[3]), "r"(b[0]), "r"(b[1]));
}
__device__ __forceinline__ void ldsm4(uint32_t r[4], uint32_t addr) {
    asm volatile("ldmatrix.sync.aligned.m8n8.x4.shared.b16 {%0,%1,%2,%3}, [%4];"
        : "=r"(r[0]), "=r"(r[1]), "=r"(r[2]), "=r"(r[3]) : "r"(addr));
}
__device__ __forceinline__ void ldsm4t(uint32_t r[4], uint32_t addr) {
    asm volatile("ldmatrix.sync.aligned.m8n8.x4.trans.shared.b16 {%0,%1,%2,%3}, [%4];"
        : "=r"(r[0]), "=r"(r[1]), "=r"(r[2]), "=r"(r[3]) : "r"(addr));
}
__device__ __forceinline__ void cpa16(void* dst, const void* src) {
    uint32_t d = (uint32_t)__cvta_generic_to_shared(dst);
    asm volatile("cp.async.cg.shared.global [%0], [%1], 16;" :: "r"(d), "l"(src) : "memory");
}
#define CP_COMMIT() asm volatile("cp.async.commit_group;" ::: "memory")
#define CP_WAIT1()  asm volatile("cp.async.wait_group 1;" ::: "memory")
#define CP_WAIT0()  asm volatile("cp.async.wait_group 0;" ::: "memory")

// ---------------- prep kernels ----------------
__global__ void rope_tables_kernel() {
    int idx = blockIdx.x * blockDim.x + threadIdx.x;
    if (idx >= SEQ * HALF) return;
    int s = idx / HALF;
    int j = idx % HALF;
    double inv = 0.61803398874989484820 / pow(10000.0, (double)j / 64.0);
    double ang = (double)s * inv;
    double si, co;
    sincos(ang, &si, &co);
    g_cos[idx] = (float)co;
    g_sin[idx] = (float)si;
}

// vectorized f32 -> f16 convert (4 elems/thread)
__global__ void conv_f16v(const float4* __restrict__ in, uint2* __restrict__ out, int n4) {
    int i = blockIdx.x * blockDim.x + threadIdx.x;
    if (i >= n4) return;
    float4 v = in[i];
    uint2 o;
    o.x = pack2h(__float2half(v.x), __float2half(v.y));
    o.y = pack2h(__float2half(v.z), __float2half(v.w));
    out[i] = o;
}

// ---------------------------------------------------------------------------
// fp16 GEMM: C = A @ W, A row-major [M,K], W row-major [K,N] consumed via
// ldmatrix.trans. cp.async double-buffered. Three epilogues:
//   gemm_mma      -> fp32 row-major C
//   gemm_mma_vt   -> transposed fp16 (V path)
//   gemm_mma_rope -> RoPE + fp16 (Q/K paths; CTA column block == one head)
// ---------------------------------------------------------------------------
#define AST 72
#define BST 136
#define ASZ (128 * AST)   // 9216 halfs
#define BSZ (64 * BST)    // 8704 halfs
#define GBUF (ASZ + BSZ)  // per-stage halfs

#define GEMM_PROLOG_AND_MAINLOOP                                                     \
    extern __shared__ __half dsm[];                                                  \
    int t    = threadIdx.x;                                                          \
    int wid  = t >> 5;                                                               \
    int lane = t & 31;                                                               \
    int wm   = (wid & 1) * 64;                                                       \
    int wn   = (wid >> 1) * 32;                                                      \
    int g    = lane >> 2;                                                            \
    int q    = lane & 3;                                                             \
    int m0 = blockIdx.y * 128;                                                       \
    int n0 = blockIdx.x * 128;                                                       \
    int lr = t >> 3;                                                                 \
    int lc = t & 7;                                                                  \
    int brow = t >> 4;                                                               \
    int bcol = t & 15;                                                               \
    int a_row = (lane & 7) + ((lane >> 3) & 1) * 8;                                  \
    int a_kof = (lane >> 4) * 8;                                                     \
    int tb_k = (lane & 7) + ((lane >> 3) & 1) * 8;                                   \
    int tb_n = (lane >> 4) * 8;                                                      \
    float acc[4][4][4];                                                              \
    _Pragma("unroll")                                                                \
    for (int mt = 0; mt < 4; mt++)                                                   \
        _Pragma("unroll")                                                            \
        for (int nt = 0; nt < 4; nt++)                                               \
            _Pragma("unroll")                                                        \
            for (int e = 0; e < 4; e++) acc[mt][nt][e] = 0.f;                        \
    uint32_t sm0 = (uint32_t)__cvta_generic_to_shared(dsm);                          \
    auto issue = [&](int ss) {                                                       \
        int k0 = ss * 64;                                                            \
        __half* As = dsm + (ss & 1) * GBUF;                                          \
        __half* Bs = As + ASZ;                                                       \
        _Pragma("unroll")                                                            \
        for (int i = 0; i < 4; i++) {                                                \
            int r = lr + i * 32;                                                     \
            cpa16(As + r * AST + lc * 8, Ah + (size_t)(m0 + r) * DM + k0 + lc * 8);  \
            int rb = brow + i * 16;                                                  \
            cpa16(Bs + rb * BST + bcol * 8,                                          \
                  Bh + (size_t)(k0 + rb) * DM + n0 + bcol * 8);                      \
        }                                                                            \
        CP_COMMIT();                                                                 \
    };                                                                               \
    issue(0);                                                                        \
    for (int ss = 0; ss < 32; ss++) {                                                \
        if (ss + 1 < 32) { issue(ss + 1); CP_WAIT1(); }                              \
        else             { CP_WAIT0(); }                                             \
        __syncthreads();                                                             \
        uint32_t asb = sm0 + (uint32_t)((ss & 1) * GBUF) * 2;                        \
        uint32_t bsb = asb + ASZ * 2;                                                \
        uint32_t aaddr = asb + (uint32_t)((wm + a_row) * AST + a_kof) * 2;           \
        uint32_t baddr = bsb + (uint32_t)(tb_k * BST + wn + tb_n) * 2;               \
        _Pragma("unroll")                                                            \
        for (int kk = 0; kk < 64; kk += 16) {                                        \
            uint32_t a[4][4], b4[2][4];                                              \
            _Pragma("unroll")                                                        \
            for (int mt = 0; mt < 4; mt++)                                           \
                ldsm4(a[mt], aaddr + (uint32_t)(mt * 16 * AST + kk) * 2);            \
            _Pragma("unroll")                                                        \
            for (int np = 0; np < 2; np++)                                           \
                ldsm4t(b4[np], baddr + (uint32_t)(kk * BST + np * 16) * 2);          \
            _Pragma("unroll")                                                        \
            for (int mt = 0; mt < 4; mt++)                                           \
                _Pragma("unroll")                                                    \
                for (int nt = 0; nt < 4; nt++)                                       \
                    mma16816(acc[mt][nt], a[mt], &b4[nt >> 1][(nt & 1) * 2]);        \
        }                                                                            \
        __syncthreads();                                                             \
    }

__global__ void __launch_bounds__(256, 2) gemm_mma(
    const __half* __restrict__ Ah, const __half* __restrict__ Bh,
    float* __restrict__ C) {
    GEMM_PROLOG_AND_MAINLOOP

    #pragma unroll
    for (int mt = 0; mt < 4; mt++) {
        int row = m0 + wm + mt * 16 + g;
        #pragma unroll
        for (int nt = 0; nt < 4; nt++) {
            int col = n0 + wn + nt * 8 + q * 2;
            *(float2*)(C + (size_t)row * DM + col)       = make_float2(acc[mt][nt][0], acc[mt][nt][1]);
            *(float2*)(C + (size_t)(row + 8) * DM + col) = make_float2(acc[mt][nt][2], acc[mt][nt][3]);
        }
    }
}

// V projection with transposed fp16 epilogue: Vt[col][row]
__global__ void __launch_bounds__(256, 2) gemm_mma_vt(
    const __half* __restrict__ Ah, const __half* __restrict__ Bh,
    __half* __restrict__ Vt) {
    GEMM_PROLOG_AND_MAINLOOP

    #pragma unroll
    for (int mt = 0; mt < 4; mt++) {
        int row = m0 + wm + mt * 16 + g;
        #pragma unroll
        for (int nt = 0; nt < 4; nt++) {
            int col = n0 + wn + nt * 8 + q * 2;
            Vt[(size_t)col * SEQ + row]           = __float2half(acc[mt][nt][0]);
            Vt[(size_t)(col + 1) * SEQ + row]     = __float2half(acc[mt][nt][1]);
            Vt[(size_t)col * SEQ + row + 8]       = __float2half(acc[mt][nt][2]);
            Vt[(size_t)(col + 1) * SEQ + row + 8] = __float2half(acc[mt][nt][3]);
        }
    }
}

// Q/K projection with fused RoPE epilogue (n-block 128 == one head).
__global__ void __launch_bounds__(256, 2) gemm_mma_rope(
    const __half* __restrict__ Ah, const __half* __restrict__ Bh,
    __half* __restrict__ Oh) {
    GEMM_PROLOG_AND_MAINLOOP

    // stage fp32 tile in smem [128][132]
    float* sf = (float*)dsm;
    #pragma unroll
    for (int mt = 0; mt < 4; mt++) {
        int r = wm + mt * 16 + g;
        #pragma unroll
        for (int nt = 0; nt < 4; nt++) {
            int c = wn + nt * 8 + q * 2;
            sf[r * 132 + c]           = acc[mt][nt][0];
            sf[r * 132 + c + 1]       = acc[mt][nt][1];
            sf[(r + 8) * 132 + c]     = acc[mt][nt][2];
            sf[(r + 8) * 132 + c + 1] = acc[mt][nt][3];
        }
    }
    __syncthreads();

    // RoPE: pair (j, j+64), head = blockIdx.x
    #pragma unroll 4
    for (int i = 0; i < 32; i++) {
        int p = t + i * 256;
        int row = p >> 6;
        int j = p & 63;
        float c1 = sf[row * 132 + j];
        float c2 = sf[row * 132 + j + 64];
        float co = g_cos[(m0 + row) * HALF + j];
        float si = g_sin[(m0 + row) * HALF + j];
        size_t base = (size_t)(m0 + row) * DM + n0 + j;
        Oh[base]        = __float2half(c1 * co - c2 * si);
        Oh[base + HALF] = __float2half(c1 * si + c2 * co);
    }
}

// ---------------------------------------------------------------------------
// Flash attention: S = Qh Kh^T (1-pass); O = Ph V (1-pass).
// ---------------------------------------------------------------------------
#define QKSTR 136
#define VSTR  72
#define QSZ (128 * QKSTR)
#define KSZ (64 * QKSTR)
#define VSZ (128 * VSTR)
#define FBUF (KSZ + VSZ)

__global__ void __launch_bounds__(256, 1) flash_mma(
    const __half* __restrict__ Qh_, const __half* __restrict__ Kh_,
    const __half* __restrict__ Vh_, __half* __restrict__ Oh_) {
    extern __shared__ __half sb[];
    __half* sQh = sb;

    int t = threadIdx.x, wid = t >> 5, lane = t & 31;
    int g = lane >> 2, q = lane & 3;
    int h  = blockIdx.y;
    int qt = (int)gridDim.x - 1 - (int)blockIdx.x;
    int q0 = qt * 128;

    int a_row = (lane & 7) + ((lane >> 3) & 1) * 8;
    int a_kof = (lane >> 4) * 8;
    int b_row = (lane & 7) + (lane >> 4) * 8;
    int b_kof = ((lane >> 3) & 1) * 8;

    uint32_t sb0 = (uint32_t)__cvta_generic_to_shared(sb);

    // Q tile load
    #pragma unroll
    for (int i = 0; i < 8; i++) {
        int idx = t + i * 256;
        int r = idx >> 4, c = idx & 15;
        cpa16(sQh + r * QKSTR + c * 8, Qh_ + (size_t)(q0 + r) * DM + h * DH + c * 8);
    }
    CP_COMMIT();

    int nkt = 2 * qt + 2;

    auto issue_kv = [&](int kt) {
        int k0 = kt * 64;
        __half* base = sb + QSZ + (kt & 1) * FBUF;
        #pragma unroll
        for (int i = 0; i < 4; i++) {
            int idx = t + i * 256;
            int rk = idx >> 4, ck = idx & 15;
            cpa16(base + rk * QKSTR + ck * 8, Kh_ + (size_t)(k0 + rk) * DM + h * DH + ck * 8);
            int rv = idx >> 3, cv = idx & 7;
            cpa16(base + KSZ + rv * VSTR + cv * 8,
                  Vh_ + (size_t)(h * DH + rv) * SEQ + k0 + cv * 8);
        }
        CP_COMMIT();
    };
    issue_kv(0);

    float o[16][4];
    #pragma unroll
    for (int nt = 0; nt < 16; nt++)
        #pragma unroll
        for (int e = 0; e < 4; e++) o[nt][e] = 0.f;
    float m0r = -1e30f, m1r = -1e30f, l0r = 0.f, l1r = 0.f;

    const float SC2 = 0.08838834764831845f * 1.4426950408889634f;
    int i0 = q0 + wid * 16 + g;

    uint32_t qa_h = sb0 + (uint32_t)(((wid * 16 + a_row) * QKSTR + a_kof) * 2);

    for (int kt = 0; kt < nkt; kt++) {
        if (kt + 1 < nkt) { issue_kv(kt + 1); CP_WAIT1(); }
        else              { CP_WAIT0(); }
        __syncthreads();

        uint32_t kb = sb0 + (uint32_t)((QSZ + (kt & 1) * FBUF) * 2)
                    + (uint32_t)((b_row * QKSTR + b_kof) * 2);
        uint32_t vb = sb0 + (uint32_t)((QSZ + (kt & 1) * FBUF + KSZ) * 2)
                    + (uint32_t)((b_row * VSTR + b_kof) * 2);
        int k0 = kt * 64;

        // ---- S = Qh Kh^T ----
        float s[8][4];
        #pragma unroll
        for (int nt = 0; nt < 8; nt++)
            #pragma unroll
            for (int e = 0; e < 4; e++) s[nt][e] = 0.f;

        #pragma unroll
        for (int kc = 0; kc < 8; kc++) {
            uint32_t a[4], b4[4][4];
            ldsm4(a, qa_h + (uint32_t)(kc * 16 * 2));
            #pragma unroll
            for (int np = 0; np < 4; np++)
                ldsm4(b4[np], kb + (uint32_t)((np * 16 * QKSTR + kc * 16) * 2));
            #pragma unroll
            for (int nt = 0; nt < 8; nt++)
                mma16816(s[nt], a, &b4[nt >> 1][(nt & 1) * 2]);
        }

        // ---- scale + causal mask ----
        bool diag = (kt >= nkt - 2);
        #pragma unroll
        for (int nt = 0; nt < 8; nt++) {
            int j0 = k0 + nt * 8 + q * 2;
            #pragma unroll
            for (int e = 0; e < 4; e++) {
                float v = s[nt][e] * SC2;
                if (diag) {
                    int i = i0 + ((e >= 2) ? 8 : 0);
                    int j = j0 + (e & 1);
                    if (j > i) v = -1e30f;
                }
                s[nt][e] = v;
            }
        }

        // ---- online softmax ----
        float mt0 = -1e30f, mt1 = -1e30f;
        #pragma unroll
        for (int nt = 0; nt < 8; nt++) {
            mt0 = fmaxf(mt0, fmaxf(s[nt][0], s[nt][1]));
            mt1 = fmaxf(mt1, fmaxf(s[nt][2], s[nt][3]));
        }
        mt0 = fmaxf(mt0, __shfl_xor_sync(0xffffffffu, mt0, 1));
        mt0 = fmaxf(mt0, __shfl_xor_sync(0xffffffffu, mt0, 2));
        mt1 = fmaxf(mt1, __shfl_xor_sync(0xffffffffu, mt1, 1));
        mt1 = fmaxf(mt1, __shfl_xor_sync(0xffffffffu, mt1, 2));
        float mn0 = fmaxf(m0r, mt0), mn1 = fmaxf(m1r, mt1);
        float al0 = ex2f(m0r - mn0), al1 = ex2f(m1r - mn1);
        m0r = mn0; m1r = mn1;

        float sum0 = 0.f, sum1 = 0.f;
        #pragma unroll
        for (int nt = 0; nt < 8; nt++) {
            s[nt][0] = ex2f(s[nt][0] - mn0);
            s[nt][1] = ex2f(s[nt][1] - mn0);
            s[nt][2] = ex2f(s[nt][2] - mn1);
            s[nt][3] = ex2f(s[nt][3] - mn1);
            sum0 += s[nt][0] + s[nt][1];
            sum1 += s[nt][2] + s[nt][3];
        }
        sum0 += __shfl_xor_sync(0xffffffffu, sum0, 1);
        sum0 += __shfl_xor_sync(0xffffffffu, sum0, 2);
        sum1 += __shfl_xor_sync(0xffffffffu, sum1, 1);
        sum1 += __shfl_xor_sync(0xffffffffu, sum1, 2);
        l0r = l0r * al0 + sum0;
        l1r = l1r * al1 + sum1;

        #pragma unroll
        for (int nt = 0; nt < 16; nt++) {
            o[nt][0] *= al0; o[nt][1] *= al0;
            o[nt][2] *= al1; o[nt][3] *= al1;
        }

        // ---- pack P (fp16) ----
        uint32_t Ph0[8], Ph1[8];
        #pragma unroll
        for (int nt = 0; nt < 8; nt++) {
            Ph0[nt] = pack2h(__float2half(s[nt][0]), __float2half(s[nt][1]));
            Ph1[nt] = pack2h(__float2half(s[nt][2]), __float2half(s[nt][3]));
        }

        // ---- O += P V ----
        #pragma unroll
        for (int kc = 0; kc < 4; kc++) {
            uint32_t a[4] = {Ph0[2 * kc], Ph1[2 * kc], Ph0[2 * kc + 1], Ph1[2 * kc + 1]};
            uint32_t b4[8][4];
            #pragma unroll
            for (int np = 0; np < 8; np++)
                ldsm4(b4[np], vb + (uint32_t)((np * 16 * VSTR + kc * 16) * 2));
            #pragma unroll
            for (int nt = 0; nt < 16; nt++)
                mma16816(o[nt], a, &b4[nt >> 1][(nt & 1) * 2]);
        }
        __syncthreads();
    }

    // ---- epilogue: normalize, convert to fp16 ----
    float inv0 = 1.f / l0r, inv1 = 1.f / l1r;
    int row0 = q0 + wid * 16 + g;
    #pragma unroll
    for (int nt = 0; nt < 16; nt++) {
        int col = h * DH + nt * 8 + q * 2;
        *(uint32_t*)(Oh_ + (size_t)row0 * DM + col) =
            pack2h(__float2half(o[nt][0] * inv0), __float2half(o[nt][1] * inv0));
        *(uint32_t*)(Oh_ + (size_t)(row0 + 8) * DM + col) =
            pack2h(__float2half(o[nt][2] * inv1), __float2half(o[nt][3] * inv1));
    }
}

// ---------------------------------------------------------------------------
extern "C" void kernel_launch(void* const* d_in, const int* in_sizes, int n_in,
                              void* d_out, int out_size) {
    const float* x  = (const float*)d_in[0];
    const float* Wq = (const float*)d_in[1];
    const float* Wk = (const float*)d_in[2];
    const float* Wv = (const float*)d_in[3];
    const float* Wo = (const float*)d_in[4];
    float* out = (float*)d_out;

    __half *xh, *wqh, *wkh, *wvh, *woh, *qh, *kh, *vth;
    cudaGetSymbolAddress((void**)&xh, g_xh);
    cudaGetSymbolAddress((void**)&wqh, g_Wqh);
    cudaGetSymbolAddress((void**)&wkh, g_Wkh);
    cudaGetSymbolAddress((void**)&wvh, g_Wvh);
    cudaGetSymbolAddress((void**)&woh, g_Woh);
    cudaGetSymbolAddress((void**)&qh, g_Qh);
    cudaGetSymbolAddress((void**)&kh, g_Kh);
    cudaGetSymbolAddress((void**)&vth, g_Vth);

    size_t gsmem = (size_t)(2 * GBUF) * sizeof(__half);   // 71680
    cudaFuncSetAttribute(gemm_mma, cudaFuncAttributeMaxDynamicSharedMemorySize, (int)gsmem);
    cudaFuncSetAttribute(gemm_mma_vt, cudaFuncAttributeMaxDynamicSharedMemorySize, (int)gsmem);
    cudaFuncSetAttribute(gemm_mma_rope, cudaFuncAttributeMaxDynamicSharedMemorySize, (int)gsmem);
    size_t fsmem = (size_t)(QSZ + 2 * FBUF) * sizeof(__half);
    cudaFuncSetAttribute(flash_mma, cudaFuncAttributeMaxDynamicSharedMemorySize, (int)fsmem);

    dim3 ggrid(DM / 128, SEQ / 128);
    int n4 = DM * DM / 4;   // weight elems / 4

    // Launch order arranged so ncu (-s 5 -c 1) captures gemm_mma_rope (launch #5).
    rope_tables_kernel<<<(SEQ * HALF + 255) / 256, 256>>>();                     // 0
    conv_f16v<<<(SEQ * DM / 4 + 255) / 256, 256>>>((const float4*)x, (uint2*)xh, SEQ * DM / 4); // 1
    conv_f16v<<<(n4 + 255) / 256, 256>>>((const float4*)Wq, (uint2*)wqh, n4);    // 2
    conv_f16v<<<(n4 + 255) / 256, 256>>>((const float4*)Wk, (uint2*)wkh, n4);    // 3
    conv_f16v<<<(n4 + 255) / 256, 256>>>((const float4*)Wv, (uint2*)wvh, n4);    // 4
    gemm_mma_rope<<<ggrid, 256, gsmem>>>(xh, wqh, qh);                           // 5  <- profiled
    gemm_mma_rope<<<ggrid, 256, gsmem>>>(xh, wkh, kh);                           // 6
    gemm_mma_vt<<<ggrid, 256, gsmem>>>(xh, wvh, vth);                            // 7
    conv_f16v<<<(n4 + 255) / 256, 256>>>((const float4*)Wo, (uint2*)woh, n4);    // 8
    flash_mma<<<dim3(SEQ / 128, NH), 256, fsmem>>>(qh, kh, vth, xh);             // 9
    gemm_mma<<<ggrid, 256, gsmem>>>(xh, woh, out);                               // 10
}

// round 15
// speedup vs baseline: 1.0019x; 1.0019x over previous
#include <cuda_runtime.h>
#include <cuda_fp16.h>
#include <math.h>
#include <stdint.h>

#define SEQ 2048
#define DM  2048
#define NH  16
#define DH  128
#define HALF 64

// ---------------- scratch (device globals; allocation-free) ----------------
__device__ float g_cos[SEQ * HALF];
__device__ float g_sin[SEQ * HALF];
__device__ __half g_xh[SEQ * DM];
__device__ __half g_Wqh[DM * DM];   // transposed [N][K] fp16
__device__ __half g_Wkh[DM * DM];
__device__ __half g_Wvh[DM * DM];
__device__ __half g_Woh[DM * DM];
__device__ __half g_Qh[SEQ * DM];
__device__ __half g_Kh[SEQ * DM];
__device__ __half g_Vth[DM * SEQ];  // V transposed: [col][seq]

// ---------------- helpers ----------------
__device__ __forceinline__ float ex2f(float x) {
    float y;
    asm("ex2.approx.ftz.f32 %0, %1;" : "=f"(y) : "f"(x));
    return y;
}
__device__ __forceinline__ uint32_t pack2h(__half lo, __half hi) {
    __half2 v; v.x = lo; v.y = hi;
    return *(uint32_t*)&v;
}
__device__ __forceinline__ void mma16816(float c[4], const uint32_t a[4], const uint32_t b[2]) {
    asm volatile(
        "mma.sync.aligned.m16n8k16.row.col.f32.f16.f16.f32 "
        "{%0,%1,%2,%3}, {%4,%5,%6,%7}, {%8,%9}, {%0,%1,%2,%3};"
        : "+f"(c[0]), "+f"(c[1]), "+f"(c[2]), "+f"(c[3])
        : "r"(a[0]), "r"(a[1]), "r"(a[2]), "r"(a[3]), "r"(b[0]), "r"(b[1]));
}
__device__ __forceinline__ void ldsm4(uint32_t r[4], uint32_t addr) {
    asm volatile("ldmatrix.sync.aligned.m8n8.x4.shared.b16 {%0,%1,%2,%3}, [%4];"
        : "=r"(r[0]), "=r"(r[1]), "=r"(r[2]), "=r"(r[3]) : "r"(addr));
}
__device__ __forceinline__ void cpa16(void* dst, const void* src) {
    uint32_t d = (uint32_t)__cvta_generic_to_shared(dst);
    asm volatile("cp.async.cg.shared.global [%0], [%1], 16;" :: "r"(d), "l"(src) : "memory");
}
#define CP_COMMIT() asm volatile("cp.async.commit_group;" ::: "memory")
#define CP_WAIT1()  asm volatile("cp.async.wait_group 1;" ::: "memory")
#define CP_WAIT0()  asm volatile("cp.async.wait_group 0;" ::: "memory")

// ---------------- prep kernels ----------------
__global__ void rope_tables_kernel() {
    int idx = blockIdx.x * blockDim.x + threadIdx.x;
    if (idx >= SEQ * HALF) return;
    int s = idx / HALF;
    int j = idx % HALF;
    double inv = 0.61803398874989484820 / pow(10000.0, (double)j / 64.0);
    double ang = (double)s * inv;
    double si, co;
    sincos(ang, &si, &co);
    g_cos[idx] = (float)co;
    g_sin[idx] = (float)si;
}

// vectorized f32 -> f16 convert (4 elems/thread)
__global__ void conv_f16v(const float4* __restrict__ in, uint2* __restrict__ out, int n4) {
    int i = blockIdx.x * blockDim.x + threadIdx.x;
    if (i >= n4) return;
    float4 v = in[i];
    uint2 o;
    o.x = pack2h(__float2half(v.x), __float2half(v.y));
    o.y = pack2h(__float2half(v.z), __float2half(v.w));
    out[i] = o;
}

// W[K][N] -> Wt [N][K] fp16; vectorized (64k x 32n tile, half2 coalesced writes)
__global__ void transpose_h(const float* __restrict__ W, __half* __restrict__ Th) {
    __shared__ float tile[32][67];
    int bk = blockIdx.y * 64;
    int bn = blockIdx.x * 32;
    int t = threadIdx.x;
    int r = t >> 5;
    int c = t & 31;
    #pragma unroll
    for (int i = 0; i < 8; i++)
        tile[c][r + i * 8] = W[(size_t)(bk + r + i * 8) * DM + bn + c];
    __syncthreads();
    #pragma unroll
    for (int i = 0; i < 4; i++) {
        int n = r + i * 8;
        __half2 v;
        v.x = __float2half(tile[n][2 * c]);
        v.y = __float2half(tile[n][2 * c + 1]);
        *(__half2*)(Th + (size_t)(bn + n) * DM + bk + 2 * c) = v;
    }
}

// ---------------------------------------------------------------------------
// fp16 GEMM (K-major B, plain ldmatrix — the fast R13 mainloop).
// Epilogues: fp32 row-major (gemm_mma), transposed fp16 (gemm_mma_vt),
// fused-RoPE fp16 (gemm_mma_rope; CTA column block == one head).
// ---------------------------------------------------------------------------
#define AST 72
#define GBUF (2 * 128 * AST)

#define GEMM_PROLOG_AND_MAINLOOP                                                     \
    extern __shared__ __half dsm[];                                                  \
    int t    = threadIdx.x;                                                          \
    int wid  = t >> 5;                                                               \
    int lane = t & 31;                                                               \
    int wm   = (wid & 1) * 64;                                                       \
    int wn   = (wid >> 1) * 32;                                                      \
    int g    = lane >> 2;                                                            \
    int q    = lane & 3;                                                             \
    int m0 = blockIdx.y * 128;                                                       \
    int n0 = blockIdx.x * 128;                                                       \
    int lr = t >> 3;                                                                 \
    int lc = t & 7;                                                                  \
    int a_row = (lane & 7) + ((lane >> 3) & 1) * 8;                                  \
    int a_kof = (lane >> 4) * 8;                                                     \
    int b_row = (lane & 7) + (lane >> 4) * 8;                                        \
    int b_kof = ((lane >> 3) & 1) * 8;                                               \
    float acc[4][4][4];                                                              \
    _Pragma("unroll")                                                                \
    for (int mt = 0; mt < 4; mt++)                                                   \
        _Pragma("unroll")                                                            \
        for (int nt = 0; nt < 4; nt++)                                               \
            _Pragma("unroll")                                                        \
            for (int e = 0; e < 4; e++) acc[mt][nt][e] = 0.f;                        \
    uint32_t sm0 = (uint32_t)__cvta_generic_to_shared(dsm);                          \
    auto issue = [&](int ss) {                                                       \
        int k0 = ss * 64;                                                            \
        __half* As = dsm + (ss & 1) * GBUF;                                          \
        __half* Bs = As + 128 * AST;                                                 \
        _Pragma("unroll")                                                            \
        for (int i = 0; i < 4; i++) {                                                \
            int r = lr + i * 32;                                                     \
            cpa16(As + r * AST + lc * 8, Ah + (size_t)(m0 + r) * DM + k0 + lc * 8);  \
            cpa16(Bs + r * AST + lc * 8, Bh + (size_t)(n0 + r) * DM + k0 + lc * 8);  \
        }                                                                            \
        CP_COMMIT();                                                                 \
    };                                                                               \
    issue(0);                                                                        \
    for (int ss = 0; ss < 32; ss++) {                                                \
        if (ss + 1 < 32) { issue(ss + 1); CP_WAIT1(); }                              \
        else             { CP_WAIT0(); }                                             \
        __syncthreads();                                                             \
        uint32_t asb = sm0 + (uint32_t)((ss & 1) * GBUF) * 2;                        \
        uint32_t bsb = asb + 128 * AST * 2;                                          \
        uint32_t aaddr = asb + (uint32_t)((wm + a_row) * AST + a_kof) * 2;           \
        uint32_t baddr = bsb + (uint32_t)((wn + b_row) * AST + b_kof) * 2;           \
        _Pragma("unroll")                                                            \
        for (int kk = 0; kk < 64; kk += 16) {                                        \
            uint32_t a[4][4], b4[2][4];                                              \
            _Pragma("unroll")                                                        \
            for (int mt = 0; mt < 4; mt++)                                           \
                ldsm4(a[mt], aaddr + (uint32_t)(mt * 16 * AST + kk) * 2);            \
            _Pragma("unroll")                                                        \
            for (int np = 0; np < 2; np++)                                           \
                ldsm4(b4[np], baddr + (uint32_t)(np * 16 * AST + kk) * 2);           \
            _Pragma("unroll")                                                        \
            for (int mt = 0; mt < 4; mt++)                                           \
                _Pragma("unroll")                                                    \
                for (int nt = 0; nt < 4; nt++)                                       \
                    mma16816(acc[mt][nt], a[mt], &b4[nt >> 1][(nt & 1) * 2]);        \
        }                                                                            \
        __syncthreads();                                                             \
    }

__global__ void __launch_bounds__(256, 2) gemm_mma(
    const __half* __restrict__ Ah, const __half* __restrict__ Bh,
    float* __restrict__ C) {
    GEMM_PROLOG_AND_MAINLOOP

    #pragma unroll
    for (int mt = 0; mt < 4; mt++) {
        int row = m0 + wm + mt * 16 + g;
        #pragma unroll
        for (int nt = 0; nt < 4; nt++) {
            int col = n0 + wn + nt * 8 + q * 2;
            *(float2*)(C + (size_t)row * DM + col)       = make_float2(acc[mt][nt][0], acc[mt][nt][1]);
            *(float2*)(C + (size_t)(row + 8) * DM + col) = make_float2(acc[mt][nt][2], acc[mt][nt][3]);
        }
    }
}

// V projection with transposed fp16 epilogue: Vt[col][row]
__global__ void __launch_bounds__(256, 2) gemm_mma_vt(
    const __half* __restrict__ Ah, const __half* __restrict__ Bh,
    __half* __restrict__ Vt) {
    GEMM_PROLOG_AND_MAINLOOP

    #pragma unroll
    for (int mt = 0; mt < 4; mt++) {
        int row = m0 + wm + mt * 16 + g;
        #pragma unroll
        for (int nt = 0; nt < 4; nt++) {
            int col = n0 + wn + nt * 8 + q * 2;
            Vt[(size_t)col * SEQ + row]           = __float2half(acc[mt][nt][0]);
            Vt[(size_t)(col + 1) * SEQ + row]     = __float2half(acc[mt][nt][1]);
            Vt[(size_t)col * SEQ + row + 8]       = __float2half(acc[mt][nt][2]);
            Vt[(size_t)(col + 1) * SEQ + row + 8] = __float2half(acc[mt][nt][3]);
        }
    }
}

// Q/K projection with fused RoPE epilogue (n-block 128 == one head).
__global__ void __launch_bounds__(256, 2) gemm_mma_rope(
    const __half* __restrict__ Ah, const __half* __restrict__ Bh,
    __half* __restrict__ Oh) {
    GEMM_PROLOG_AND_MAINLOOP

    // stage fp32 tile in smem [128][132] (fits in the 72KB dynamic smem)
    float* sf = (float*)dsm;
    #pragma unroll
    for (int mt = 0; mt < 4; mt++) {
        int r = wm + mt * 16 + g;
        #pragma unroll
        for (int nt = 0; nt < 4; nt++) {
            int c = wn + nt * 8 + q * 2;
            sf[r * 132 + c]           = acc[mt][nt][0];
            sf[r * 132 + c + 1]       = acc[mt][nt][1];
            sf[(r + 8) * 132 + c]     = acc[mt][nt][2];
            sf[(r + 8) * 132 + c + 1] = acc[mt][nt][3];
        }
    }
    __syncthreads();

    // RoPE: pair (j, j+64); head = blockIdx.x
    #pragma unroll 4
    for (int i = 0; i < 32; i++) {
        int p = t + i * 256;
        int row = p >> 6;
        int j = p & 63;
        float c1 = sf[row * 132 + j];
        float c2 = sf[row * 132 + j + 64];
        float co = g_cos[(m0 + row) * HALF + j];
        float si = g_sin[(m0 + row) * HALF + j];
        size_t base = (size_t)(m0 + row) * DM + n0 + j;
        Oh[base]        = __float2half(c1 * co - c2 * si);
        Oh[base + HALF] = __float2half(c1 * si + c2 * co);
    }
}

// ---------------------------------------------------------------------------
// Flash attention: S = Qh Kh^T (1-pass); O = Ph V (1-pass).
// ---------------------------------------------------------------------------
#define QKSTR 136
#define VSTR  72
#define QSZ (128 * QKSTR)
#define KSZ (64 * QKSTR)
#define VSZ (128 * VSTR)
#define FBUF (KSZ + VSZ)

__global__ void __launch_bounds__(256, 1) flash_mma(
    const __half* __restrict__ Qh_, const __half* __restrict__ Kh_,
    const __half* __restrict__ Vh_, __half* __restrict__ Oh_) {
    extern __shared__ __half sb[];
    __half* sQh = sb;

    int t = threadIdx.x, wid = t >> 5, lane = t & 31;
    int g = lane >> 2, q = lane & 3;
    int h  = blockIdx.y;
    int qt = (int)gridDim.x - 1 - (int)blockIdx.x;
    int q0 = qt * 128;

    int a_row = (lane & 7) + ((lane >> 3) & 1) * 8;
    int a_kof = (lane >> 4) * 8;
    int b_row = (lane & 7) + (lane >> 4) * 8;
    int b_kof = ((lane >> 3) & 1) * 8;

    uint32_t sb0 = (uint32_t)__cvta_generic_to_shared(sb);

    // Q tile load
    #pragma unroll
    for (int i = 0; i < 8; i++) {
        int idx = t + i * 256;
        int r = idx >> 4, c = idx & 15;
        cpa16(sQh + r * QKSTR + c * 8, Qh_ + (size_t)(q0 + r) * DM + h * DH + c * 8);
    }
    CP_COMMIT();

    int nkt = 2 * qt + 2;

    auto issue_kv = [&](int kt) {
        int k0 = kt * 64;
        __half* base = sb + QSZ + (kt & 1) * FBUF;
        #pragma unroll
        for (int i = 0; i < 4; i++) {
            int idx = t + i * 256;
            int rk = idx >> 4, ck = idx & 15;
            cpa16(base + rk * QKSTR + ck * 8, Kh_ + (size_t)(k0 + rk) * DM + h * DH + ck * 8);
            int rv = idx >> 3, cv = idx & 7;
            cpa16(base + KSZ + rv * VSTR + cv * 8,
                  Vh_ + (size_t)(h * DH + rv) * SEQ + k0 + cv * 8);
        }
        CP_COMMIT();
    };
    issue_kv(0);

    float o[16][4];
    #pragma unroll
    for (int nt = 0; nt < 16; nt++)
        #pragma unroll
        for (int e = 0; e < 4; e++) o[nt][e] = 0.f;
    float m0r = -1e30f, m1r = -1e30f, l0r = 0.f, l1r = 0.f;

    const float SC2 = 0.08838834764831845f * 1.4426950408889634f;
    int i0 = q0 + wid * 16 + g;

    uint32_t qa_h = sb0 + (uint32_t)(((wid * 16 + a_row) * QKSTR + a_kof) * 2);

    for (int kt = 0; kt < nkt; kt++) {
        if (kt + 1 < nkt) { issue_kv(kt + 1); CP_WAIT1(); }
        else              { CP_WAIT0(); }
        __syncthreads();

        uint32_t kb = sb0 + (uint32_t)((QSZ + (kt & 1) * FBUF) * 2)
                    + (uint32_t)((b_row * QKSTR + b_kof) * 2);
        uint32_t vb = sb0 + (uint32_t)((QSZ + (kt & 1) * FBUF + KSZ) * 2)
                    + (uint32_t)((b_row * VSTR + b_kof) * 2);
        int k0 = kt * 64;

        // ---- S = Qh Kh^T ----
        float s[8][4];
        #pragma unroll
        for (int nt = 0; nt < 8; nt++)
            #pragma unroll
            for (int e = 0; e < 4; e++) s[nt][e] = 0.f;

        #pragma unroll
        for (int kc = 0; kc < 8; kc++) {
            uint32_t a[4], b4[4][4];
            ldsm4(a, qa_h + (uint32_t)(kc * 16 * 2));
            #pragma unroll
            for (int np = 0; np < 4; np++)
                ldsm4(b4[np], kb + (uint32_t)((np * 16 * QKSTR + kc * 16) * 2));
            #pragma unroll
            for (int nt = 0; nt < 8; nt++)
                mma16816(s[nt], a, &b4[nt >> 1][(nt & 1) * 2]);
        }

        // ---- scale + causal mask ----
        bool diag = (kt >= nkt - 2);
        #pragma unroll
        for (int nt = 0; nt < 8; nt++) {
            int j0 = k0 + nt * 8 + q * 2;
            #pragma unroll
            for (int e = 0; e < 4; e++) {
                float v = s[nt][e] * SC2;
                if (diag) {
                    int i = i0 + ((e >= 2) ? 8 : 0);
                    int j = j0 + (e & 1);
                    if (j > i) v = -1e30f;
                }
                s[nt][e] = v;
            }
        }

        // ---- online softmax ----
        float mt0 = -1e30f, mt1 = -1e30f;
        #pragma unroll
        for (int nt = 0; nt < 8; nt++) {
            mt0 = fmaxf(mt0, fmaxf(s[nt][0], s[nt][1]));
            mt1 = fmaxf(mt1, fmaxf(s[nt][2], s[nt][3]));
        }
        mt0 = fmaxf(mt0, __shfl_xor_sync(0xffffffffu, mt0, 1));
        mt0 = fmaxf(mt0, __shfl_xor_sync(0xffffffffu, mt0, 2));
        mt1 = fmaxf(mt1, __shfl_xor_sync(0xffffffffu, mt1, 1));
        mt1 = fmaxf(mt1, __shfl_xor_sync(0xffffffffu, mt1, 2));
        float mn0 = fmaxf(m0r, mt0), mn1 = fmaxf(m1r, mt1);
        float al0 = ex2f(m0r - mn0), al1 = ex2f(m1r - mn1);
        m0r = mn0; m1r = mn1;

        float sum0 = 0.f, sum1 = 0.f;
        #pragma unroll
        for (int nt = 0; nt < 8; nt++) {
            s[nt][0] = ex2f(s[nt][0] - mn0);
            s[nt][1] = ex2f(s[nt][1] - mn0);
            s[nt][2] = ex2f(s[nt][2] - mn1);
            s[nt][3] = ex2f(s[nt][3] - mn1);
            sum0 += s[nt][0] + s[nt][1];
            sum1 += s[nt][2] + s[nt][3];
        }
        sum0 += __shfl_xor_sync(0xffffffffu, sum0, 1);
        sum0 += __shfl_xor_sync(0xffffffffu, sum0, 2);
        sum1 += __shfl_xor_sync(0xffffffffu, sum1, 1);
        sum1 += __shfl_xor_sync(0xffffffffu, sum1, 2);
        l0r = l0r * al0 + sum0;
        l1r = l1r * al1 + sum1;

        #pragma unroll
        for (int nt = 0; nt < 16; nt++) {
            o[nt][0] *= al0; o[nt][1] *= al0;
            o[nt][2] *= al1; o[nt][3] *= al1;
        }

        // ---- pack P (fp16) ----
        uint32_t Ph0[8], Ph1[8];
        #pragma unroll
        for (int nt = 0; nt < 8; nt++) {
            Ph0[nt] = pack2h(__float2half(s[nt][0]), __float2half(s[nt][1]));
            Ph1[nt] = pack2h(__float2half(s[nt][2]), __float2half(s[nt][3]));
        }

        // ---- O += P V ----
        #pragma unroll
        for (int kc = 0; kc < 4; kc++) {
            uint32_t a[4] = {Ph0[2 * kc], Ph1[2 * kc], Ph0[2 * kc + 1], Ph1[2 * kc + 1]};
            uint32_t b4[8][4];
            #pragma unroll
            for (int np = 0; np < 8; np++)
                ldsm4(b4[np], vb + (uint32_t)((np * 16 * VSTR + kc * 16) * 2));
            #pragma unroll
            for (int nt = 0; nt < 16; nt++)
                mma16816(o[nt], a, &b4[nt >> 1][(nt & 1) * 2]);
        }
        __syncthreads();
    }

    // ---- epilogue: normalize, convert to fp16 ----
    float inv0 = 1.f / l0r, inv1 = 1.f / l1r;
    int row0 = q0 + wid * 16 + g;
    #pragma unroll
    for (int nt = 0; nt < 16; nt++) {
        int col = h * DH + nt * 8 + q * 2;
        *(uint32_t*)(Oh_ + (size_t)row0 * DM + col) =
            pack2h(__float2half(o[nt][0] * inv0), __float2half(o[nt][1] * inv0));
        *(uint32_t*)(Oh_ + (size_t)(row0 + 8) * DM + col) =
            pack2h(__float2half(o[nt][2] * inv1), __float2half(o[nt][3] * inv1));
    }
}

// ---------------------------------------------------------------------------
extern "C" void kernel_launch(void* const* d_in, const int* in_sizes, int n_in,
                              void* d_out, int out_size) {
    const float* x  = (const float*)d_in[0];
    const float* Wq = (const float*)d_in[1];
    const float* Wk = (const float*)d_in[2];
    const float* Wv = (const float*)d_in[3];
    const float* Wo = (const float*)d_in[4];
    float* out = (float*)d_out;

    __half *xh, *wqh, *wkh, *wvh, *woh, *qh, *kh, *vth;
    cudaGetSymbolAddress((void**)&xh, g_xh);
    cudaGetSymbolAddress((void**)&wqh, g_Wqh);
    cudaGetSymbolAddress((void**)&wkh, g_Wkh);
    cudaGetSymbolAddress((void**)&wvh, g_Wvh);
    cudaGetSymbolAddress((void**)&woh, g_Woh);
    cudaGetSymbolAddress((void**)&qh, g_Qh);
    cudaGetSymbolAddress((void**)&kh, g_Kh);
    cudaGetSymbolAddress((void**)&vth, g_Vth);

    size_t gsmem = (size_t)(2 * GBUF) * sizeof(__half);   // 73728
    cudaFuncSetAttribute(gemm_mma, cudaFuncAttributeMaxDynamicSharedMemorySize, (int)gsmem);
    cudaFuncSetAttribute(gemm_mma_vt, cudaFuncAttributeMaxDynamicSharedMemorySize, (int)gsmem);
    cudaFuncSetAttribute(gemm_mma_rope, cudaFuncAttributeMaxDynamicSharedMemorySize, (int)gsmem);
    size_t fsmem = (size_t)(QSZ + 2 * FBUF) * sizeof(__half);
    cudaFuncSetAttribute(flash_mma, cudaFuncAttributeMaxDynamicSharedMemorySize, (int)fsmem);

    dim3 tgrid(DM / 32, DM / 64), tblk(256);
    dim3 ggrid(DM / 128, SEQ / 128);

    // Launch order arranged so ncu (-s 5 -c 1) captures gemm_mma_rope (launch #5).
    rope_tables_kernel<<<(SEQ * HALF + 255) / 256, 256>>>();                     // 0
    conv_f16v<<<(SEQ * DM / 4 + 255) / 256, 256>>>((const float4*)x, (uint2*)xh, SEQ * DM / 4); // 1
    transpose_h<<<tgrid, tblk>>>(Wq, wqh);                                       // 2
    transpose_h<<<tgrid, tblk>>>(Wk, wkh);                                       // 3
    transpose_h<<<tgrid, tblk>>>(Wv, wvh);                                       // 4
    gemm_mma_rope<<<ggrid, 256, gsmem>>>(xh, wqh, qh);                           // 5  <- profiled
    gemm_mma_rope<<<ggrid, 256, gsmem>>>(xh, wkh, kh);                           // 6
    gemm_mma_vt<<<ggrid, 256, gsmem>>>(xh, wvh, vth);                            // 7
    transpose_h<<<tgrid, tblk>>>(Wo, woh);                                       // 8
    flash_mma<<<dim3(SEQ / 128, NH), 256, fsmem>>>(qh, kh, vth, xh);             // 9
    gemm_mma<<<ggrid, 256, gsmem>>>(xh, woh, out);                               // 10
}

// round 16
// speedup vs baseline: 1.0087x; 1.0069x over previous
#include <cuda_runtime.h>
#include <cuda_fp16.h>
#include <math.h>
#include <stdint.h>

#define SEQ 2048
#define DM  2048
#define NH  16
#define DH  128
#define HALF 64

// ---------------- scratch (device globals; allocation-free) ----------------
__device__ float g_Q[SEQ * DM];
__device__ float g_K[SEQ * DM];
__device__ float g_cos[SEQ * HALF];
__device__ float g_sin[SEQ * HALF];
__device__ __half g_xh[SEQ * DM];
__device__ __half g_Wqh[DM * DM];   // transposed [N][K] fp16
__device__ __half g_Wkh[DM * DM];
__device__ __half g_Wvh[DM * DM];
__device__ __half g_Woh[DM * DM];
__device__ __half g_Qh[SEQ * DM];
__device__ __half g_Kh[SEQ * DM];
__device__ __half g_Vth[DM * SEQ];  // V transposed: [col][seq]

// ---------------- helpers ----------------
__device__ __forceinline__ float ex2f(float x) {
    float y;
    asm("ex2.approx.ftz.f32 %0, %1;" : "=f"(y) : "f"(x));
    return y;
}
__device__ __forceinline__ uint32_t pack2h(__half lo, __half hi) {
    __half2 v; v.x = lo; v.y = hi;
    return *(uint32_t*)&v;
}
__device__ __forceinline__ void mma16816(float c[4], const uint32_t a[4], const uint32_t b[2]) {
    asm volatile(
        "mma.sync.aligned.m16n8k16.row.col.f32.f16.f16.f32 "
        "{%0,%1,%2,%3}, {%4,%5,%6,%7}, {%8,%9}, {%0,%1,%2,%3};"
        : "+f"(c[0]), "+f"(c[1]), "+f"(c[2]), "+f"(c[3])
        : "r"(a[0]), "r"(a[1]), "r"(a[2]), "r"(a[3]), "r"(b[0]), "r"(b[1]));
}
__device__ __forceinline__ void ldsm4(uint32_t r[4], uint32_t addr) {
    asm volatile("ldmatrix.sync.aligned.m8n8.x4.shared.b16 {%0,%1,%2,%3}, [%4];"
        : "=r"(r[0]), "=r"(r[1]), "=r"(r[2]), "=r"(r[3]) : "r"(addr));
}
__device__ __forceinline__ void cpa16(void* dst, const void* src) {
    uint32_t d = (uint32_t)__cvta_generic_to_shared(dst);
    asm volatile("cp.async.cg.shared.global [%0], [%1], 16;" :: "r"(d), "l"(src) : "memory");
}
#define CP_COMMIT() asm volatile("cp.async.commit_group;" ::: "memory")
#define CP_WAIT1()  asm volatile("cp.async.wait_group 1;" ::: "memory")
#define CP_WAIT0()  asm volatile("cp.async.wait_group 0;" ::: "memory")

// ---------------- prep kernels ----------------
__global__ void rope_tables_kernel() {
    int idx = blockIdx.x * blockDim.x + threadIdx.x;
    if (idx >= SEQ * HALF) return;
    int s = idx / HALF;
    int j = idx % HALF;
    double inv = 0.61803398874989484820 / pow(10000.0, (double)j / 64.0);
    double ang = (double)s * inv;
    double si, co;
    sincos(ang, &si, &co);
    g_cos[idx] = (float)co;
    g_sin[idx] = (float)si;
}

// RoPE -> Qh, Kh fp16
__global__ void rope_apply_split() {
    int idx = blockIdx.x * blockDim.x + threadIdx.x;
    if (idx >= SEQ * NH * HALF) return;
    int s   = idx / (NH * HALF);
    int rem = idx % (NH * HALF);
    int h   = rem / HALF;
    int j   = rem % HALF;
    int base = s * DM + h * DH + j;
    float c  = g_cos[s * HALF + j];
    float sn = g_sin[s * HALF + j];

    float q1 = g_Q[base], q2 = g_Q[base + HALF];
    g_Qh[base]        = __float2half(q1 * c - q2 * sn);
    g_Qh[base + HALF] = __float2half(q1 * sn + q2 * c);

    float k1 = g_K[base], k2 = g_K[base + HALF];
    g_Kh[base]        = __float2half(k1 * c - k2 * sn);
    g_Kh[base + HALF] = __float2half(k1 * sn + k2 * c);
}

// vectorized f32 -> f16 convert (4 elems/thread)
__global__ void conv_f16v(const float4* __restrict__ in, uint2* __restrict__ out, int n4) {
    int i = blockIdx.x * blockDim.x + threadIdx.x;
    if (i >= n4) return;
    float4 v = in[i];
    uint2 o;
    o.x = pack2h(__float2half(v.x), __float2half(v.y));
    o.y = pack2h(__float2half(v.z), __float2half(v.w));
    out[i] = o;
}

// W[K][N] -> Wt [N][K] fp16; vectorized (64k x 32n tile, half2 coalesced writes)
__global__ void transpose_h(const float* __restrict__ W, __half* __restrict__ Th) {
    __shared__ float tile[32][67];
    int bk = blockIdx.y * 64;
    int bn = blockIdx.x * 32;
    int t = threadIdx.x;
    int r = t >> 5;
    int c = t & 31;
    #pragma unroll
    for (int i = 0; i < 8; i++)
        tile[c][r + i * 8] = W[(size_t)(bk + r + i * 8) * DM + bn + c];
    __syncthreads();
    #pragma unroll
    for (int i = 0; i < 4; i++) {
        int n = r + i * 8;
        __half2 v;
        v.x = __float2half(tile[n][2 * c]);
        v.y = __float2half(tile[n][2 * c + 1]);
        *(__half2*)(Th + (size_t)(bn + n) * DM + bk + 2 * c) = v;
    }
}

// ---------------------------------------------------------------------------
// fp16 GEMM (K-major B, plain ldmatrix). Epilogues: fp32 row-major (gemm_mma),
// transposed fp16 (gemm_mma_vt).
// ---------------------------------------------------------------------------
#define AST 72
#define GBUF (2 * 128 * AST)

#define GEMM_PROLOG_AND_MAINLOOP                                                     \
    extern __shared__ __half dsm[];                                                  \
    int t    = threadIdx.x;                                                          \
    int wid  = t >> 5;                                                               \
    int lane = t & 31;                                                               \
    int wm   = (wid & 1) * 64;                                                       \
    int wn   = (wid >> 1) * 32;                                                      \
    int g    = lane >> 2;                                                            \
    int q    = lane & 3;                                                             \
    int m0 = blockIdx.y * 128;                                                       \
    int n0 = blockIdx.x * 128;                                                       \
    int lr = t >> 3;                                                                 \
    int lc = t & 7;                                                                  \
    int a_row = (lane & 7) + ((lane >> 3) & 1) * 8;                                  \
    int a_kof = (lane >> 4) * 8;                                                     \
    int b_row = (lane & 7) + (lane >> 4) * 8;                                        \
    int b_kof = ((lane >> 3) & 1) * 8;                                               \
    float acc[4][4][4];                                                              \
    _Pragma("unroll")                                                                \
    for (int mt = 0; mt < 4; mt++)                                                   \
        _Pragma("unroll")                                                            \
        for (int nt = 0; nt < 4; nt++)                                               \
            _Pragma("unroll")                                                        \
            for (int e = 0; e < 4; e++) acc[mt][nt][e] = 0.f;                        \
    uint32_t sm0 = (uint32_t)__cvta_generic_to_shared(dsm);                          \
    auto issue = [&](int ss) {                                                       \
        int k0 = ss * 64;                                                            \
        __half* As = dsm + (ss & 1) * GBUF;                                          \
        __half* Bs = As + 128 * AST;                                                 \
        _Pragma("unroll")                                                            \
        for (int i = 0; i < 4; i++) {                                                \
            int r = lr + i * 32;                                                     \
            cpa16(As + r * AST + lc * 8, Ah + (size_t)(m0 + r) * DM + k0 + lc * 8);  \
            cpa16(Bs + r * AST + lc * 8, Bh + (size_t)(n0 + r) * DM + k0 + lc * 8);  \
        }                                                                            \
        CP_COMMIT();                                                                 \
    };                                                                               \
    issue(0);                                                                        \
    for (int ss = 0; ss < 32; ss++) {                                                \
        if (ss + 1 < 32) { issue(ss + 1); CP_WAIT1(); }                              \
        else             { CP_WAIT0(); }                                             \
        __syncthreads();                                                             \
        uint32_t asb = sm0 + (uint32_t)((ss & 1) * GBUF) * 2;                        \
        uint32_t bsb = asb + 128 * AST * 2;                                          \
        uint32_t aaddr = asb + (uint32_t)((wm + a_row) * AST + a_kof) * 2;           \
        uint32_t baddr = bsb + (uint32_t)((wn + b_row) * AST + b_kof) * 2;           \
        _Pragma("unroll")                                                            \
        for (int kk = 0; kk < 64; kk += 16) {                                        \
            uint32_t a[4][4], b4[2][4];                                              \
            _Pragma("unroll")                                                        \
            for (int mt = 0; mt < 4; mt++)                                           \
                ldsm4(a[mt], aaddr + (uint32_t)(mt * 16 * AST + kk) * 2);            \
            _Pragma("unroll")                                                        \
            for (int np = 0; np < 2; np++)                                           \
                ldsm4(b4[np], baddr + (uint32_t)(np * 16 * AST + kk) * 2);           \
            _Pragma("unroll")                                                        \
            for (int mt = 0; mt < 4; mt++)                                           \
                _Pragma("unroll")                                                    \
                for (int nt = 0; nt < 4; nt++)                                       \
                    mma16816(acc[mt][nt], a[mt], &b4[nt >> 1][(nt & 1) * 2]);        \
        }                                                                            \
        __syncthreads();                                                             \
    }

__global__ void __launch_bounds__(256, 2) gemm_mma(
    const __half* __restrict__ Ah, const __half* __restrict__ Bh,
    float* __restrict__ C) {
    GEMM_PROLOG_AND_MAINLOOP

    #pragma unroll
    for (int mt = 0; mt < 4; mt++) {
        int row = m0 + wm + mt * 16 + g;
        #pragma unroll
        for (int nt = 0; nt < 4; nt++) {
            int col = n0 + wn + nt * 8 + q * 2;
            *(float2*)(C + (size_t)row * DM + col)       = make_float2(acc[mt][nt][0], acc[mt][nt][1]);
            *(float2*)(C + (size_t)(row + 8) * DM + col) = make_float2(acc[mt][nt][2], acc[mt][nt][3]);
        }
    }
}

// V projection with transposed fp16 epilogue: Vt[col][row]
__global__ void __launch_bounds__(256, 2) gemm_mma_vt(
    const __half* __restrict__ Ah, const __half* __restrict__ Bh,
    __half* __restrict__ Vt) {
    GEMM_PROLOG_AND_MAINLOOP

    #pragma unroll
    for (int mt = 0; mt < 4; mt++) {
        int row = m0 + wm + mt * 16 + g;
        #pragma unroll
        for (int nt = 0; nt < 4; nt++) {
            int col = n0 + wn + nt * 8 + q * 2;
            Vt[(size_t)col * SEQ + row]           = __float2half(acc[mt][nt][0]);
            Vt[(size_t)(col + 1) * SEQ + row]     = __float2half(acc[mt][nt][1]);
            Vt[(size_t)col * SEQ + row + 8]       = __float2half(acc[mt][nt][2]);
            Vt[(size_t)(col + 1) * SEQ + row + 8] = __float2half(acc[mt][nt][3]);
        }
    }
}

// ---------------------------------------------------------------------------
// Flash attention: S = Qh Kh^T (1-pass); O = Ph V (1-pass).
// occ=2: two CTAs/SM (2 x 106496 B smem fits); single wave for 256 CTAs.
// ---------------------------------------------------------------------------
#define QKSTR 136
#define VSTR  72
#define QSZ (128 * QKSTR)
#define KSZ (64 * QKSTR)
#define VSZ (128 * VSTR)
#define FBUF (KSZ + VSZ)

__global__ void __launch_bounds__(256, 2) flash_mma(
    const __half* __restrict__ Qh_, const __half* __restrict__ Kh_,
    const __half* __restrict__ Vh_, __half* __restrict__ Oh_) {
    extern __shared__ __half sb[];
    __half* sQh = sb;

    int t = threadIdx.x, wid = t >> 5, lane = t & 31;
    int g = lane >> 2, q = lane & 3;
    int h  = blockIdx.y;
    int qt = (int)gridDim.x - 1 - (int)blockIdx.x;
    int q0 = qt * 128;

    int a_row = (lane & 7) + ((lane >> 3) & 1) * 8;
    int a_kof = (lane >> 4) * 8;
    int b_row = (lane & 7) + (lane >> 4) * 8;
    int b_kof = ((lane >> 3) & 1) * 8;

    uint32_t sb0 = (uint32_t)__cvta_generic_to_shared(sb);

    // Q tile load
    #pragma unroll
    for (int i = 0; i < 8; i++) {
        int idx = t + i * 256;
        int r = idx >> 4, c = idx & 15;
        cpa16(sQh + r * QKSTR + c * 8, Qh_ + (size_t)(q0 + r) * DM + h * DH + c * 8);
    }
    CP_COMMIT();

    int nkt = 2 * qt + 2;

    auto issue_kv = [&](int kt) {
        int k0 = kt * 64;
        __half* base = sb + QSZ + (kt & 1) * FBUF;
        #pragma unroll
        for (int i = 0; i < 4; i++) {
            int idx = t + i * 256;
            int rk = idx >> 4, ck = idx & 15;
            cpa16(base + rk * QKSTR + ck * 8, Kh_ + (size_t)(k0 + rk) * DM + h * DH + ck * 8);
            int rv = idx >> 3, cv = idx & 7;
            cpa16(base + KSZ + rv * VSTR + cv * 8,
                  Vh_ + (size_t)(h * DH + rv) * SEQ + k0 + cv * 8);
        }
        CP_COMMIT();
    };
    issue_kv(0);

    float o[16][4];
    #pragma unroll
    for (int nt = 0; nt < 16; nt++)
        #pragma unroll
        for (int e = 0; e < 4; e++) o[nt][e] = 0.f;
    float m0r = -1e30f, m1r = -1e30f, l0r = 0.f, l1r = 0.f;

    const float SC2 = 0.08838834764831845f * 1.4426950408889634f;
    int i0 = q0 + wid * 16 + g;

    uint32_t qa_h = sb0 + (uint32_t)(((wid * 16 + a_row) * QKSTR + a_kof) * 2);

    for (int kt = 0; kt < nkt; kt++) {
        if (kt + 1 < nkt) { issue_kv(kt + 1); CP_WAIT1(); }
        else              { CP_WAIT0(); }
        __syncthreads();

        uint32_t kb = sb0 + (uint32_t)((QSZ + (kt & 1) * FBUF) * 2)
                    + (uint32_t)((b_row * QKSTR + b_kof) * 2);
        uint32_t vb = sb0 + (uint32_t)((QSZ + (kt & 1) * FBUF + KSZ) * 2)
                    + (uint32_t)((b_row * VSTR + b_kof) * 2);
        int k0 = kt * 64;

        // ---- S = Qh Kh^T ----
        float s[8][4];
        #pragma unroll
        for (int nt = 0; nt < 8; nt++)
            #pragma unroll
            for (int e = 0; e < 4; e++) s[nt][e] = 0.f;

        #pragma unroll
        for (int kc = 0; kc < 8; kc++) {
            uint32_t a[4], b4[4][4];
            ldsm4(a, qa_h + (uint32_t)(kc * 16 * 2));
            #pragma unroll
            for (int np = 0; np < 4; np++)
                ldsm4(b4[np], kb + (uint32_t)((np * 16 * QKSTR + kc * 16) * 2));
            #pragma unroll
            for (int nt = 0; nt < 8; nt++)
                mma16816(s[nt], a, &b4[nt >> 1][(nt & 1) * 2]);
        }

        // ---- scale + causal mask ----
        bool diag = (kt >= nkt - 2);
        #pragma unroll
        for (int nt = 0; nt < 8; nt++) {
            int j0 = k0 + nt * 8 + q * 2;
            #pragma unroll
            for (int e = 0; e < 4; e++) {
                float v = s[nt][e] * SC2;
                if (diag) {
                    int i = i0 + ((e >= 2) ? 8 : 0);
                    int j = j0 + (e & 1);
                    if (j > i) v = -1e30f;
                }
                s[nt][e] = v;
            }
        }

        // ---- online softmax ----
        float mt0 = -1e30f, mt1 = -1e30f;
        #pragma unroll
        for (int nt = 0; nt < 8; nt++) {
            mt0 = fmaxf(mt0, fmaxf(s[nt][0], s[nt][1]));
            mt1 = fmaxf(mt1, fmaxf(s[nt][2], s[nt][3]));
        }
        mt0 = fmaxf(mt0, __shfl_xor_sync(0xffffffffu, mt0, 1));
        mt0 = fmaxf(mt0, __shfl_xor_sync(0xffffffffu, mt0, 2));
        mt1 = fmaxf(mt1, __shfl_xor_sync(0xffffffffu, mt1, 1));
        mt1 = fmaxf(mt1, __shfl_xor_sync(0xffffffffu, mt1, 2));
        float mn0 = fmaxf(m0r, mt0), mn1 = fmaxf(m1r, mt1);
        float al0 = ex2f(m0r - mn0), al1 = ex2f(m1r - mn1);
        m0r = mn0; m1r = mn1;

        float sum0 = 0.f, sum1 = 0.f;
        #pragma unroll
        for (int nt = 0; nt < 8; nt++) {
            s[nt][0] = ex2f(s[nt][0] - mn0);
            s[nt][1] = ex2f(s[nt][1] - mn0);
            s[nt][2] = ex2f(s[nt][2] - mn1);
            s[nt][3] = ex2f(s[nt][3] - mn1);
            sum0 += s[nt][0] + s[nt][1];
            sum1 += s[nt][2] + s[nt][3];
        }
        sum0 += __shfl_xor_sync(0xffffffffu, sum0, 1);
        sum0 += __shfl_xor_sync(0xffffffffu, sum0, 2);
        sum1 += __shfl_xor_sync(0xffffffffu, sum1, 1);
        sum1 += __shfl_xor_sync(0xffffffffu, sum1, 2);
        l0r = l0r * al0 + sum0;
        l1r = l1r * al1 + sum1;

        #pragma unroll
        for (int nt = 0; nt < 16; nt++) {
            o[nt][0] *= al0; o[nt][1] *= al0;
            o[nt][2] *= al1; o[nt][3] *= al1;
        }

        // ---- pack P (fp16) ----
        uint32_t Ph0[8], Ph1[8];
        #pragma unroll
        for (int nt = 0; nt < 8; nt++) {
            Ph0[nt] = pack2h(__float2half(s[nt][0]), __float2half(s[nt][1]));
            Ph1[nt] = pack2h(__float2half(s[nt][2]), __float2half(s[nt][3]));
        }

        // ---- O += P V ----
        #pragma unroll
        for (int kc = 0; kc < 4; kc++) {
            uint32_t a[4] = {Ph0[2 * kc], Ph1[2 * kc], Ph0[2 * kc + 1], Ph1[2 * kc + 1]};
            uint32_t b4[8][4];
            #pragma unroll
            for (int np = 0; np < 8; np++)
                ldsm4(b4[np], vb + (uint32_t)((np * 16 * VSTR + kc * 16) * 2));
            #pragma unroll
            for (int nt = 0; nt < 16; nt++)
                mma16816(o[nt], a, &b4[nt >> 1][(nt & 1) * 2]);
        }
        __syncthreads();
    }

    // ---- epilogue: normalize, convert to fp16 ----
    float inv0 = 1.f / l0r, inv1 = 1.f / l1r;
    int row0 = q0 + wid * 16 + g;
    #pragma unroll
    for (int nt = 0; nt < 16; nt++) {
        int col = h * DH + nt * 8 + q * 2;
        *(uint32_t*)(Oh_ + (size_t)row0 * DM + col) =
            pack2h(__float2half(o[nt][0] * inv0), __float2half(o[nt][1] * inv0));
        *(uint32_t*)(Oh_ + (size_t)(row0 + 8) * DM + col) =
            pack2h(__float2half(o[nt][2] * inv1), __float2half(o[nt][3] * inv1));
    }
}

// ---------------------------------------------------------------------------
extern "C" void kernel_launch(void* const* d_in, const int* in_sizes, int n_in,
                              void* d_out, int out_size) {
    const float* x  = (const float*)d_in[0];
    const float* Wq = (const float*)d_in[1];
    const float* Wk = (const float*)d_in[2];
    const float* Wv = (const float*)d_in[3];
    const float* Wo = (const float*)d_in[4];
    float* out = (float*)d_out;

    float *pQ, *pK;
    cudaGetSymbolAddress((void**)&pQ, g_Q);
    cudaGetSymbolAddress((void**)&pK, g_K);
    __half *xh, *wqh, *wkh, *wvh, *woh, *qh, *kh, *vth;
    cudaGetSymbolAddress((void**)&xh, g_xh);
    cudaGetSymbolAddress((void**)&wqh, g_Wqh);
    cudaGetSymbolAddress((void**)&wkh, g_Wkh);
    cudaGetSymbolAddress((void**)&wvh, g_Wvh);
    cudaGetSymbolAddress((void**)&woh, g_Woh);
    cudaGetSymbolAddress((void**)&qh, g_Qh);
    cudaGetSymbolAddress((void**)&kh, g_Kh);
    cudaGetSymbolAddress((void**)&vth, g_Vth);

    size_t gsmem = (size_t)(2 * GBUF) * sizeof(__half);   // 73728
    cudaFuncSetAttribute(gemm_mma, cudaFuncAttributeMaxDynamicSharedMemorySize, (int)gsmem);
    cudaFuncSetAttribute(gemm_mma_vt, cudaFuncAttributeMaxDynamicSharedMemorySize, (int)gsmem);
    size_t fsmem = (size_t)(QSZ + 2 * FBUF) * sizeof(__half);   // 106496
    cudaFuncSetAttribute(flash_mma, cudaFuncAttributeMaxDynamicSharedMemorySize, (int)fsmem);

    dim3 tgrid(DM / 32, DM / 64), tblk(256);
    dim3 ggrid(DM / 128, SEQ / 128);

    // Launch order arranged so ncu (-s 5 -c 1) captures gemm_mma (launch #5).
    rope_tables_kernel<<<(SEQ * HALF + 255) / 256, 256>>>();                     // 0
    conv_f16v<<<(SEQ * DM / 4 + 255) / 256, 256>>>((const float4*)x, (uint2*)xh, SEQ * DM / 4); // 1
    transpose_h<<<tgrid, tblk>>>(Wq, wqh);                                       // 2
    transpose_h<<<tgrid, tblk>>>(Wk, wkh);                                       // 3
    transpose_h<<<tgrid, tblk>>>(Wv, wvh);                                       // 4
    gemm_mma<<<ggrid, 256, gsmem>>>(xh, wqh, pQ);                                // 5  <- profiled
    gemm_mma<<<ggrid, 256, gsmem>>>(xh, wkh, pK);                                // 6
    gemm_mma_vt<<<ggrid, 256, gsmem>>>(xh, wvh, vth);                            // 7
    rope_apply_split<<<(SEQ * NH * HALF) / 256, 256>>>();                        // 8
    transpose_h<<<tgrid, tblk>>>(Wo, woh);                                       // 9
    flash_mma<<<dim3(SEQ / 128, NH), 256, fsmem>>>(qh, kh, vth, xh);             // 10
    gemm_mma<<<ggrid, 256, gsmem>>>(xh, woh, out);                               // 11
}

// round 17
// speedup vs baseline: 1.0499x; 1.0409x over previous
#include <cuda_runtime.h>
#include <cuda_fp16.h>
#include <math.h>
#include <stdint.h>

#define SEQ 2048
#define DM  2048
#define NH  16
#define DH  128
#define HALF 64

// ---------------- scratch (device globals; allocation-free) ----------------
__device__ float g_Q[SEQ * DM];
__device__ float g_K[SEQ * DM];
__device__ float g_cos[SEQ * HALF];
__device__ float g_sin[SEQ * HALF];
__device__ __half g_xh[SEQ * DM];
__device__ __half g_Wqh[DM * DM];   // transposed [N][K] fp16
__device__ __half g_Wkh[DM * DM];
__device__ __half g_Wvh[DM * DM];
__device__ __half g_Woh[DM * DM];
__device__ __half g_Qh[SEQ * DM];
__device__ __half g_Kh[SEQ * DM];
__device__ __half g_Vth[DM * SEQ];  // V transposed: [col][seq]

// ---------------- helpers ----------------
__device__ __forceinline__ float ex2f(float x) {
    float y;
    asm("ex2.approx.ftz.f32 %0, %1;" : "=f"(y) : "f"(x));
    return y;
}
__device__ __forceinline__ uint32_t pack2h(__half lo, __half hi) {
    __half2 v; v.x = lo; v.y = hi;
    return *(uint32_t*)&v;
}
__device__ __forceinline__ void mma16816(float c[4], const uint32_t a[4], const uint32_t b[2]) {
    asm volatile(
        "mma.sync.aligned.m16n8k16.row.col.f32.f16.f16.f32 "
        "{%0,%1,%2,%3}, {%4,%5,%6,%7}, {%8,%9}, {%0,%1,%2,%3};"
        : "+f"(c[0]), "+f"(c[1]), "+f"(c[2]), "+f"(c[3])
        : "r"(a[0]), "r"(a[1]), "r"(a[2]), "r"(a[3]), "r"(b[0]), "r"(b[1]));
}
__device__ __forceinline__ void ldsm4(uint32_t r[4], uint32_t addr) {
    asm volatile("ldmatrix.sync.aligned.m8n8.x4.shared.b16 {%0,%1,%2,%3}, [%4];"
        : "=r"(r[0]), "=r"(r[1]), "=r"(r[2]), "=r"(r[3]) : "r"(addr));
}
__device__ __forceinline__ void cpa16(void* dst, const void* src) {
    uint32_t d = (uint32_t)__cvta_generic_to_shared(dst);
    asm volatile("cp.async.cg.shared.global [%0], [%1], 16;" :: "r"(d), "l"(src) : "memory");
}
#define CP_COMMIT() asm volatile("cp.async.commit_group;" ::: "memory")
#define CP_WAIT1()  asm volatile("cp.async.wait_group 1;" ::: "memory")
#define CP_WAIT0()  asm volatile("cp.async.wait_group 0;" ::: "memory")

// ---------------- prep kernels ----------------
__global__ void rope_tables_kernel() {
    int idx = blockIdx.x * blockDim.x + threadIdx.x;
    if (idx >= SEQ * HALF) return;
    int s = idx / HALF;
    int j = idx % HALF;
    double inv = 0.61803398874989484820 / pow(10000.0, (double)j / 64.0);
    double ang = (double)s * inv;
    double si, co;
    sincos(ang, &si, &co);
    g_cos[idx] = (float)co;
    g_sin[idx] = (float)si;
}

// RoPE -> Qh, Kh fp16
__global__ void rope_apply_split() {
    int idx = blockIdx.x * blockDim.x + threadIdx.x;
    if (idx >= SEQ * NH * HALF) return;
    int s   = idx / (NH * HALF);
    int rem = idx % (NH * HALF);
    int h   = rem / HALF;
    int j   = rem % HALF;
    int base = s * DM + h * DH + j;
    float c  = g_cos[s * HALF + j];
    float sn = g_sin[s * HALF + j];

    float q1 = g_Q[base], q2 = g_Q[base + HALF];
    g_Qh[base]        = __float2half(q1 * c - q2 * sn);
    g_Qh[base + HALF] = __float2half(q1 * sn + q2 * c);

    float k1 = g_K[base], k2 = g_K[base + HALF];
    g_Kh[base]        = __float2half(k1 * c - k2 * sn);
    g_Kh[base + HALF] = __float2half(k1 * sn + k2 * c);
}

// vectorized f32 -> f16 convert (4 elems/thread)
__global__ void conv_f16v(const float4* __restrict__ in, uint2* __restrict__ out, int n4) {
    int i = blockIdx.x * blockDim.x + threadIdx.x;
    if (i >= n4) return;
    float4 v = in[i];
    uint2 o;
    o.x = pack2h(__float2half(v.x), __float2half(v.y));
    o.y = pack2h(__float2half(v.z), __float2half(v.w));
    out[i] = o;
}

// W[K][N] -> Wt [N][K] fp16; vectorized (64k x 32n tile, half2 coalesced writes)
__global__ void transpose_h(const float* __restrict__ W, __half* __restrict__ Th) {
    __shared__ float tile[32][67];
    int bk = blockIdx.y * 64;
    int bn = blockIdx.x * 32;
    int t = threadIdx.x;
    int r = t >> 5;
    int c = t & 31;
    #pragma unroll
    for (int i = 0; i < 8; i++)
        tile[c][r + i * 8] = W[(size_t)(bk + r + i * 8) * DM + bn + c];
    __syncthreads();
    #pragma unroll
    for (int i = 0; i < 4; i++) {
        int n = r + i * 8;
        __half2 v;
        v.x = __float2half(tile[n][2 * c]);
        v.y = __float2half(tile[n][2 * c + 1]);
        *(__half2*)(Th + (size_t)(bn + n) * DM + bk + 2 * c) = v;
    }
}

// ---------------------------------------------------------------------------
// fp16 GEMM (K-major B, plain ldmatrix). Epilogues: fp32 row-major (gemm_mma),
// transposed fp16 (gemm_mma_vt).
// ---------------------------------------------------------------------------
#define AST 72
#define GBUF (2 * 128 * AST)

#define GEMM_PROLOG_AND_MAINLOOP                                                     \
    extern __shared__ __half dsm[];                                                  \
    int t    = threadIdx.x;                                                          \
    int wid  = t >> 5;                                                               \
    int lane = t & 31;                                                               \
    int wm   = (wid & 1) * 64;                                                       \
    int wn   = (wid >> 1) * 32;                                                      \
    int g    = lane >> 2;                                                            \
    int q    = lane & 3;                                                             \
    int m0 = blockIdx.y * 128;                                                       \
    int n0 = blockIdx.x * 128;                                                       \
    int lr = t >> 3;                                                                 \
    int lc = t & 7;                                                                  \
    int a_row = (lane & 7) + ((lane >> 3) & 1) * 8;                                  \
    int a_kof = (lane >> 4) * 8;                                                     \
    int b_row = (lane & 7) + (lane >> 4) * 8;                                        \
    int b_kof = ((lane >> 3) & 1) * 8;                                               \
    float acc[4][4][4];                                                              \
    _Pragma("unroll")                                                                \
    for (int mt = 0; mt < 4; mt++)                                                   \
        _Pragma("unroll")                                                            \
        for (int nt = 0; nt < 4; nt++)                                               \
            _Pragma("unroll")                                                        \
            for (int e = 0; e < 4; e++) acc[mt][nt][e] = 0.f;                        \
    uint32_t sm0 = (uint32_t)__cvta_generic_to_shared(dsm);                          \
    auto issue = [&](int ss) {                                                       \
        int k0 = ss * 64;                                                            \
        __half* As = dsm + (ss & 1) * GBUF;                                          \
        __half* Bs = As + 128 * AST;                                                 \
        _Pragma("unroll")                                                            \
        for (int i = 0; i < 4; i++) {                                                \
            int r = lr + i * 32;                                                     \
            cpa16(As + r * AST + lc * 8, Ah + (size_t)(m0 + r) * DM + k0 + lc * 8);  \
            cpa16(Bs + r * AST + lc * 8, Bh + (size_t)(n0 + r) * DM + k0 + lc * 8);  \
        }                                                                            \
        CP_COMMIT();                                                                 \
    };                                                                               \
    issue(0);                                                                        \
    for (int ss = 0; ss < 32; ss++) {                                                \
        if (ss + 1 < 32) { issue(ss + 1); CP_WAIT1(); }                              \
        else             { CP_WAIT0(); }                                             \
        __syncthreads();                                                             \
        uint32_t asb = sm0 + (uint32_t)((ss & 1) * GBUF) * 2;                        \
        uint32_t bsb = asb + 128 * AST * 2;                                          \
        uint32_t aaddr = asb + (uint32_t)((wm + a_row) * AST + a_kof) * 2;           \
        uint32_t baddr = bsb + (uint32_t)((wn + b_row) * AST + b_kof) * 2;           \
        _Pragma("unroll")                                                            \
        for (int kk = 0; kk < 64; kk += 16) {                                        \
            uint32_t a[4][4], b4[2][4];                                              \
            _Pragma("unroll")                                                        \
            for (int mt = 0; mt < 4; mt++)                                           \
                ldsm4(a[mt], aaddr + (uint32_t)(mt * 16 * AST + kk) * 2);            \
            _Pragma("unroll")                                                        \
            for (int np = 0; np < 2; np++)                                           \
                ldsm4(b4[np], baddr + (uint32_t)(np * 16 * AST + kk) * 2);           \
            _Pragma("unroll")                                                        \
            for (int mt = 0; mt < 4; mt++)                                           \
                _Pragma("unroll")                                                    \
                for (int nt = 0; nt < 4; nt++)                                       \
                    mma16816(acc[mt][nt], a[mt], &b4[nt >> 1][(nt & 1) * 2]);        \
        }                                                                            \
        __syncthreads();                                                             \
    }

__global__ void __launch_bounds__(256, 2) gemm_mma(
    const __half* __restrict__ Ah, const __half* __restrict__ Bh,
    float* __restrict__ C) {
    GEMM_PROLOG_AND_MAINLOOP

    #pragma unroll
    for (int mt = 0; mt < 4; mt++) {
        int row = m0 + wm + mt * 16 + g;
        #pragma unroll
        for (int nt = 0; nt < 4; nt++) {
            int col = n0 + wn + nt * 8 + q * 2;
            *(float2*)(C + (size_t)row * DM + col)       = make_float2(acc[mt][nt][0], acc[mt][nt][1]);
            *(float2*)(C + (size_t)(row + 8) * DM + col) = make_float2(acc[mt][nt][2], acc[mt][nt][3]);
        }
    }
}

// V projection with transposed fp16 epilogue: Vt[col][row]
__global__ void __launch_bounds__(256, 2) gemm_mma_vt(
    const __half* __restrict__ Ah, const __half* __restrict__ Bh,
    __half* __restrict__ Vt) {
    GEMM_PROLOG_AND_MAINLOOP

    #pragma unroll
    for (int mt = 0; mt < 4; mt++) {
        int row = m0 + wm + mt * 16 + g;
        #pragma unroll
        for (int nt = 0; nt < 4; nt++) {
            int col = n0 + wn + nt * 8 + q * 2;
            Vt[(size_t)col * SEQ + row]           = __float2half(acc[mt][nt][0]);
            Vt[(size_t)(col + 1) * SEQ + row]     = __float2half(acc[mt][nt][1]);
            Vt[(size_t)col * SEQ + row + 8]       = __float2half(acc[mt][nt][2]);
            Vt[(size_t)(col + 1) * SEQ + row + 8] = __float2half(acc[mt][nt][3]);
        }
    }
}

// ---------------------------------------------------------------------------
// Flash attention, K-tile = 128: S = Qh Kh^T (1-pass); O = Ph V (1-pass).
// Halves the per-iteration softmax/rescale/barrier overhead vs BK=64.
// ---------------------------------------------------------------------------
#define QKSTR 136
#define QSZ (128 * QKSTR)
#define KSZ (128 * QKSTR)     // K tile: 128 seq rows x 128 dh
#define VSZ (128 * QKSTR)     // V tile: 128 dh rows x 128 seq
#define FBUF (KSZ + VSZ)

__global__ void __launch_bounds__(256, 1) flash_mma(
    const __half* __restrict__ Qh_, const __half* __restrict__ Kh_,
    const __half* __restrict__ Vh_, __half* __restrict__ Oh_) {
    extern __shared__ __half sb[];
    __half* sQh = sb;

    int t = threadIdx.x, wid = t >> 5, lane = t & 31;
    int g = lane >> 2, q = lane & 3;
    int h  = blockIdx.y;
    int qt = (int)gridDim.x - 1 - (int)blockIdx.x;
    int q0 = qt * 128;

    int a_row = (lane & 7) + ((lane >> 3) & 1) * 8;
    int a_kof = (lane >> 4) * 8;
    int b_row = (lane & 7) + (lane >> 4) * 8;
    int b_kof = ((lane >> 3) & 1) * 8;

    uint32_t sb0 = (uint32_t)__cvta_generic_to_shared(sb);

    // Q tile load
    #pragma unroll
    for (int i = 0; i < 8; i++) {
        int idx = t + i * 256;
        int r = idx >> 4, c = idx & 15;
        cpa16(sQh + r * QKSTR + c * 8, Qh_ + (size_t)(q0 + r) * DM + h * DH + c * 8);
    }
    CP_COMMIT();

    int nkt = qt + 1;

    auto issue_kv = [&](int kt) {
        int k0 = kt * 128;
        __half* base = sb + QSZ + (kt & 1) * FBUF;
        #pragma unroll
        for (int i = 0; i < 8; i++) {
            int idx = t + i * 256;
            int r = idx >> 4, c = idx & 15;
            cpa16(base + r * QKSTR + c * 8, Kh_ + (size_t)(k0 + r) * DM + h * DH + c * 8);
            cpa16(base + KSZ + r * QKSTR + c * 8,
                  Vh_ + (size_t)(h * DH + r) * SEQ + k0 + c * 8);
        }
        CP_COMMIT();
    };
    issue_kv(0);

    float o[16][4];
    #pragma unroll
    for (int nt = 0; nt < 16; nt++)
        #pragma unroll
        for (int e = 0; e < 4; e++) o[nt][e] = 0.f;
    float m0r = -1e30f, m1r = -1e30f, l0r = 0.f, l1r = 0.f;

    const float SC2 = 0.08838834764831845f * 1.4426950408889634f;
    int i0 = q0 + wid * 16 + g;

    uint32_t qa_h = sb0 + (uint32_t)(((wid * 16 + a_row) * QKSTR + a_kof) * 2);

    for (int kt = 0; kt < nkt; kt++) {
        if (kt + 1 < nkt) { issue_kv(kt + 1); CP_WAIT1(); }
        else              { CP_WAIT0(); }
        __syncthreads();

        uint32_t kb = sb0 + (uint32_t)((QSZ + (kt & 1) * FBUF) * 2)
                    + (uint32_t)((b_row * QKSTR + b_kof) * 2);
        uint32_t vb = sb0 + (uint32_t)((QSZ + (kt & 1) * FBUF + KSZ) * 2)
                    + (uint32_t)((b_row * QKSTR + b_kof) * 2);
        int k0 = kt * 128;

        // ---- S = Qh Kh^T : 16 nt covering 128 keys ----
        float s[16][4];
        #pragma unroll
        for (int nt = 0; nt < 16; nt++)
            #pragma unroll
            for (int e = 0; e < 4; e++) s[nt][e] = 0.f;

        #pragma unroll
        for (int kc = 0; kc < 8; kc++) {
            uint32_t a[4];
            ldsm4(a, qa_h + (uint32_t)(kc * 16 * 2));
            #pragma unroll
            for (int np = 0; np < 8; np++) {
                uint32_t b4[4];
                ldsm4(b4, kb + (uint32_t)((np * 16 * QKSTR + kc * 16) * 2));
                mma16816(s[2 * np],     a, &b4[0]);
                mma16816(s[2 * np + 1], a, &b4[2]);
            }
        }

        // ---- scale + causal mask (only last tile is diagonal) ----
        bool diag = (kt == nkt - 1);
        #pragma unroll
        for (int nt = 0; nt < 16; nt++) {
            int j0 = k0 + nt * 8 + q * 2;
            #pragma unroll
            for (int e = 0; e < 4; e++) {
                float v = s[nt][e] * SC2;
                if (diag) {
                    int i = i0 + ((e >= 2) ? 8 : 0);
                    int j = j0 + (e & 1);
                    if (j > i) v = -1e30f;
                }
                s[nt][e] = v;
            }
        }

        // ---- online softmax ----
        float mt0 = -1e30f, mt1 = -1e30f;
        #pragma unroll
        for (int nt = 0; nt < 16; nt++) {
            mt0 = fmaxf(mt0, fmaxf(s[nt][0], s[nt][1]));
            mt1 = fmaxf(mt1, fmaxf(s[nt][2], s[nt][3]));
        }
        mt0 = fmaxf(mt0, __shfl_xor_sync(0xffffffffu, mt0, 1));
        mt0 = fmaxf(mt0, __shfl_xor_sync(0xffffffffu, mt0, 2));
        mt1 = fmaxf(mt1, __shfl_xor_sync(0xffffffffu, mt1, 1));
        mt1 = fmaxf(mt1, __shfl_xor_sync(0xffffffffu, mt1, 2));
        float mn0 = fmaxf(m0r, mt0), mn1 = fmaxf(m1r, mt1);
        float al0 = ex2f(m0r - mn0), al1 = ex2f(m1r - mn1);
        m0r = mn0; m1r = mn1;

        float sum0 = 0.f, sum1 = 0.f;
        #pragma unroll
        for (int nt = 0; nt < 16; nt++) {
            s[nt][0] = ex2f(s[nt][0] - mn0);
            s[nt][1] = ex2f(s[nt][1] - mn0);
            s[nt][2] = ex2f(s[nt][2] - mn1);
            s[nt][3] = ex2f(s[nt][3] - mn1);
            sum0 += s[nt][0] + s[nt][1];
            sum1 += s[nt][2] + s[nt][3];
        }
        sum0 += __shfl_xor_sync(0xffffffffu, sum0, 1);
        sum0 += __shfl_xor_sync(0xffffffffu, sum0, 2);
        sum1 += __shfl_xor_sync(0xffffffffu, sum1, 1);
        sum1 += __shfl_xor_sync(0xffffffffu, sum1, 2);
        l0r = l0r * al0 + sum0;
        l1r = l1r * al1 + sum1;

        #pragma unroll
        for (int nt = 0; nt < 16; nt++) {
            o[nt][0] *= al0; o[nt][1] *= al0;
            o[nt][2] *= al1; o[nt][3] *= al1;
        }

        // ---- pack P (fp16) ----
        uint32_t Ph0[16], Ph1[16];
        #pragma unroll
        for (int nt = 0; nt < 16; nt++) {
            Ph0[nt] = pack2h(__float2half(s[nt][0]), __float2half(s[nt][1]));
            Ph1[nt] = pack2h(__float2half(s[nt][2]), __float2half(s[nt][3]));
        }

        // ---- O += P V (k over 128 keys = 8 chunks) ----
        #pragma unroll
        for (int kc = 0; kc < 8; kc++) {
            uint32_t a[4] = {Ph0[2 * kc], Ph1[2 * kc], Ph0[2 * kc + 1], Ph1[2 * kc + 1]};
            #pragma unroll
            for (int np = 0; np < 8; np++) {
                uint32_t b4[4];
                ldsm4(b4, vb + (uint32_t)((np * 16 * QKSTR + kc * 16) * 2));
                mma16816(o[2 * np],     a, &b4[0]);
                mma16816(o[2 * np + 1], a, &b4[2]);
            }
        }
        __syncthreads();
    }

    // ---- epilogue: normalize, convert to fp16 ----
    float inv0 = 1.f / l0r, inv1 = 1.f / l1r;
    int row0 = q0 + wid * 16 + g;
    #pragma unroll
    for (int nt = 0; nt < 16; nt++) {
        int col = h * DH + nt * 8 + q * 2;
        *(uint32_t*)(Oh_ + (size_t)row0 * DM + col) =
            pack2h(__float2half(o[nt][0] * inv0), __float2half(o[nt][1] * inv0));
        *(uint32_t*)(Oh_ + (size_t)(row0 + 8) * DM + col) =
            pack2h(__float2half(o[nt][2] * inv1), __float2half(o[nt][3] * inv1));
    }
}

// ---------------------------------------------------------------------------
extern "C" void kernel_launch(void* const* d_in, const int* in_sizes, int n_in,
                              void* d_out, int out_size) {
    const float* x  = (const float*)d_in[0];
    const float* Wq = (const float*)d_in[1];
    const float* Wk = (const float*)d_in[2];
    const float* Wv = (const float*)d_in[3];
    const float* Wo = (const float*)d_in[4];
    float* out = (float*)d_out;

    float *pQ, *pK;
    cudaGetSymbolAddress((void**)&pQ, g_Q);
    cudaGetSymbolAddress((void**)&pK, g_K);
    __half *xh, *wqh, *wkh, *wvh, *woh, *qh, *kh, *vth;
    cudaGetSymbolAddress((void**)&xh, g_xh);
    cudaGetSymbolAddress((void**)&wqh, g_Wqh);
    cudaGetSymbolAddress((void**)&wkh, g_Wkh);
    cudaGetSymbolAddress((void**)&wvh, g_Wvh);
    cudaGetSymbolAddress((void**)&woh, g_Woh);
    cudaGetSymbolAddress((void**)&qh, g_Qh);
    cudaGetSymbolAddress((void**)&kh, g_Kh);
    cudaGetSymbolAddress((void**)&vth, g_Vth);

    size_t gsmem = (size_t)(2 * GBUF) * sizeof(__half);     // 73728
    cudaFuncSetAttribute(gemm_mma, cudaFuncAttributeMaxDynamicSharedMemorySize, (int)gsmem);
    cudaFuncSetAttribute(gemm_mma_vt, cudaFuncAttributeMaxDynamicSharedMemorySize, (int)gsmem);
    size_t fsmem = (size_t)(QSZ + 2 * FBUF) * sizeof(__half);  // 174080
    cudaFuncSetAttribute(flash_mma, cudaFuncAttributeMaxDynamicSharedMemorySize, (int)fsmem);

    dim3 tgrid(DM / 32, DM / 64), tblk(256);
    dim3 ggrid(DM / 128, SEQ / 128);

    // Launch order arranged so ncu (-s 5 -c 1) captures gemm_mma (launch #5).
    rope_tables_kernel<<<(SEQ * HALF + 255) / 256, 256>>>();                     // 0
    conv_f16v<<<(SEQ * DM / 4 + 255) / 256, 256>>>((const float4*)x, (uint2*)xh, SEQ * DM / 4); // 1
    transpose_h<<<tgrid, tblk>>>(Wq, wqh);                                       // 2
    transpose_h<<<tgrid, tblk>>>(Wk, wkh);                                       // 3
    transpose_h<<<tgrid, tblk>>>(Wv, wvh);                                       // 4
    gemm_mma<<<ggrid, 256, gsmem>>>(xh, wqh, pQ);                                // 5  <- profiled
    gemm_mma<<<ggrid, 256, gsmem>>>(xh, wkh, pK);                                // 6
    gemm_mma_vt<<<ggrid, 256, gsmem>>>(xh, wvh, vth);                            // 7
    rope_apply_split<<<(SEQ * NH * HALF) / 256, 256>>>();                        // 8
    transpose_h<<<tgrid, tblk>>>(Wo, woh);                                       // 9
    flash_mma<<<dim3(SEQ / 128, NH), 256, fsmem>>>(qh, kh, vth, xh);             // 10
    gemm_mma<<<ggrid, 256, gsmem>>>(xh, woh, out);                               // 11
}